// round 10
// baseline (speedup 1.0000x reference)
#include <cuda_runtime.h>
#include <cuda_fp16.h>
#include <math.h>

// Problem constants (fixed by the dataset)
#define NN    100000
#define EMAX  1600000
#define E2MAX 3200000   // 2 * EMAX
#define DIN   192
#define HH    64
#define DOUTT 32
#define CC    2
#define GG    256

typedef unsigned long long u64;

// Scratch (static device arrays -- no allocation allowed)
__device__ __align__(16) float  g_h  [NN * HH];   // node features (fp32)
__device__ __align__(16) __half g_hwh[NN * HH];   // h @ W, fp16 gather payload
__device__ float g_dis[NN];          // deg^{-1/2}
__device__ int   g_deg[NN];          // degree (no self-loop)
__device__ int   g_rowstart[NN + 1]; // CSR row offsets
__device__ __align__(16) int2 g_rank[EMAX];  // (rank in src list, rank in dst list)
__device__ __align__(16) int2 g_adjc[E2MAX]; // (neighbor, coef bits)
__device__ __align__(16) float g_pool[GG * HH];
__device__ float g_cnt [GG];

__device__ __forceinline__ void red_add_v2(float2* addr, float a, float b) {
    asm volatile("red.global.add.v2.f32 [%0], {%1, %2};"
                 :: "l"(addr), "f"(a), "f"(b)
                 : "memory");
}

// ---- packed f32x2 helpers (sm_100+) ---------------------------------------
__device__ __forceinline__ u64 pk2(float x, float y) {
    u64 r;
    asm("mov.b64 %0, {%1, %2};" : "=l"(r) : "f"(x), "f"(y));
    return r;
}
__device__ __forceinline__ void upk2(u64 v, float* x, float* y) {
    asm("mov.b64 {%0, %1}, %2;" : "=f"(*x), "=f"(*y) : "l"(v));
}
__device__ __forceinline__ u64 fma2(u64 a, u64 b, u64 c) {
    u64 d;
    asm("fma.rn.f32x2 %0, %1, %2, %3;" : "=l"(d) : "l"(a), "l"(b), "l"(c));
    return d;
}

// ---------------------------------------------------------------------------
__global__ void k_init() {
    int i = blockIdx.x * blockDim.x + threadIdx.x;
    if (i < NN) g_deg[i] = 0;
    if (i < GG * HH) g_pool[i] = 0.0f;
    if (i < GG) g_cnt[i] = 0.0f;
}

// Degree histogram; keep the returned rank so the fill pass needs no atomics.
__global__ void k_degree(const int* __restrict__ src,
                         const int* __restrict__ dst, int E) {
    int i = blockIdx.x * blockDim.x + threadIdx.x;
    if (i >= E) return;
    int s = src[i], d = dst[i];
    int rs = atomicAdd(&g_deg[s], 1);
    int rd = atomicAdd(&g_deg[d], 1);
    g_rank[i] = make_int2(rs, rd);
}

// Exclusive scan of degrees -> rowstart, plus dis.
#define SCAN_T 1024
__global__ void k_scan(int N) {
    __shared__ int sums[SCAN_T];
    int t = threadIdx.x;
    int chunk = (N + SCAN_T - 1) / SCAN_T;
    int beg = t * chunk;
    int end = min(beg + chunk, N);
    int s = 0;
    for (int i = beg; i < end; i++) s += g_deg[i];
    sums[t] = s;
    __syncthreads();
    if (t == 0) {
        int run = 0;
        for (int u = 0; u < SCAN_T; u++) {
            int v = sums[u];
            sums[u] = run;       // exclusive prefix
            run += v;
        }
        g_rowstart[N] = run;     // total = 2E
    }
    __syncthreads();
    int run = sums[t];
    for (int i = beg; i < end; i++) {
        int d = g_deg[i];
        g_rowstart[i] = run;
        g_dis[i] = rsqrtf((float)d + 1.0f);
        run += d;
    }
}

// CSR fill, atomic-free: slot = rowstart[node] + precomputed rank.
__global__ void k_fill_adj(const int* __restrict__ src,
                           const int* __restrict__ dst, int E) {
    int i = blockIdx.x * blockDim.x + threadIdx.x;
    if (i >= E) return;
    int s = src[i], d = dst[i];
    int2 r = g_rank[i];
    float c = g_dis[s] * g_dis[d];
    int ci = __float_as_int(c);
    g_adjc[g_rowstart[s] + r.x] = make_int2(d, ci);
    g_adjc[g_rowstart[d] + r.y] = make_int2(s, ci);
}

// ---------------------------------------------------------------------------
// Write one row-chunk of 8 fp32 values as 8 fp16 (one uint4) to g_hwh.
__device__ __forceinline__ void store_h8(int row, int tc, const float* v) {
    __half2 h0 = __floats2half2_rn(v[0], v[1]);
    __half2 h1 = __floats2half2_rn(v[2], v[3]);
    __half2 h2 = __floats2half2_rn(v[4], v[5]);
    __half2 h3 = __floats2half2_rn(v[6], v[7]);
    uint4 u;
    u.x = *(unsigned*)&h0;
    u.y = *(unsigned*)&h1;
    u.z = *(unsigned*)&h2;
    u.w = *(unsigned*)&h3;
    ((uint4*)g_hwh)[row * 8 + tc] = u;
}

// ---------------------------------------------------------------------------
// Fused: g_hwh = fp16( relu(x @ W_in + b_in) @ W1 ).  h never hits gmem.
// Block tile 128 rows, 128 threads, 8x8 register tile, BK=16, f32x2 FMA.
__global__ void k_gemm_fused(const float* __restrict__ x,
                             const float* __restrict__ W,
                             const float* __restrict__ bias,
                             const float* __restrict__ W1, int N) {
    __shared__ __align__(16) float As[16][128];
    __shared__ __align__(16) float Ws[16][64];
    __shared__ __align__(16) float Hs[64][128];   // transposed h: Hs[feat][row]
    int t  = threadIdx.x;
    int tr = t >> 3;                // 0..15
    int tc = t & 7;                 // 0..7
    int row0 = blockIdx.x * 128;

    u64 acc2[8][4];
    #pragma unroll
    for (int i = 0; i < 8; i++)
        #pragma unroll
        for (int j = 0; j < 4; j++) acc2[i][j] = 0ULL;

    // ---- GEMM 1: x[128 x 192] @ W_in[192 x 64] ----
    for (int kt = 0; kt < DIN; kt += 16) {
        {
            int gr = row0 + t;
            float4 v0, v1, v2, v3;
            if (gr < N) {
                const float4* Ar = (const float4*)(x + (long)gr * DIN + kt);
                v0 = Ar[0]; v1 = Ar[1]; v2 = Ar[2]; v3 = Ar[3];
            } else {
                v0 = make_float4(0.f,0.f,0.f,0.f); v1 = v0; v2 = v0; v3 = v0;
            }
            As[ 0][t] = v0.x; As[ 1][t] = v0.y; As[ 2][t] = v0.z; As[ 3][t] = v0.w;
            As[ 4][t] = v1.x; As[ 5][t] = v1.y; As[ 6][t] = v1.z; As[ 7][t] = v1.w;
            As[ 8][t] = v2.x; As[ 9][t] = v2.y; As[10][t] = v2.z; As[11][t] = v2.w;
            As[12][t] = v3.x; As[13][t] = v3.y; As[14][t] = v3.z; As[15][t] = v3.w;
        }
        {
            const float4* Wg = (const float4*)(W + kt * 64);
            ((float4*)Ws)[t]       = Wg[t];
            ((float4*)Ws)[t + 128] = Wg[t + 128];
        }
        __syncthreads();
        #pragma unroll
        for (int k = 0; k < 16; k++) {
            float4 a0 = *(const float4*)&As[k][tr * 8];
            float4 a1 = *(const float4*)&As[k][tr * 8 + 4];
            const u64* bw = (const u64*)&Ws[k][tc * 8];
            u64 b0 = bw[0], b1 = bw[1], b2 = bw[2], b3 = bw[3];
            float a[8];
            a[0]=a0.x; a[1]=a0.y; a[2]=a0.z; a[3]=a0.w;
            a[4]=a1.x; a[5]=a1.y; a[6]=a1.z; a[7]=a1.w;
            #pragma unroll
            for (int i = 0; i < 8; i++) {
                u64 aa = pk2(a[i], a[i]);
                acc2[i][0] = fma2(aa, b0, acc2[i][0]);
                acc2[i][1] = fma2(aa, b1, acc2[i][1]);
                acc2[i][2] = fma2(aa, b2, acc2[i][2]);
                acc2[i][3] = fma2(aa, b3, acc2[i][3]);
            }
        }
        __syncthreads();
    }

    // Epilogue 1: h = relu(acc + bias), transposed into Hs[feat][row].
    {
        float4 bb0 = ((const float4*)bias)[tc * 2];
        float4 bb1 = ((const float4*)bias)[tc * 2 + 1];
        float bv[8];
        bv[0]=bb0.x; bv[1]=bb0.y; bv[2]=bb0.z; bv[3]=bb0.w;
        bv[4]=bb1.x; bv[5]=bb1.y; bv[6]=bb1.z; bv[7]=bb1.w;
        #pragma unroll
        for (int i = 0; i < 8; i++) {
            float o[8];
            upk2(acc2[i][0], &o[0], &o[1]);
            upk2(acc2[i][1], &o[2], &o[3]);
            upk2(acc2[i][2], &o[4], &o[5]);
            upk2(acc2[i][3], &o[6], &o[7]);
            #pragma unroll
            for (int j = 0; j < 8; j++)
                Hs[tc * 8 + j][tr * 8 + i] = fmaxf(o[j] + bv[j], 0.0f);
        }
    }
    __syncthreads();

    // ---- GEMM 2: h[128 x 64] @ W1[64 x 64] ----
    #pragma unroll
    for (int i = 0; i < 8; i++)
        #pragma unroll
        for (int j = 0; j < 4; j++) acc2[i][j] = 0ULL;

    for (int kt = 0; kt < HH; kt += 16) {
        {
            const float4* Wg = (const float4*)(W1 + kt * 64);
            ((float4*)Ws)[t]       = Wg[t];
            ((float4*)Ws)[t + 128] = Wg[t + 128];
        }
        __syncthreads();
        #pragma unroll
        for (int k = 0; k < 16; k++) {
            float4 a0 = *(const float4*)&Hs[kt + k][tr * 8];
            float4 a1 = *(const float4*)&Hs[kt + k][tr * 8 + 4];
            const u64* bw = (const u64*)&Ws[k][tc * 8];
            u64 b0 = bw[0], b1 = bw[1], b2 = bw[2], b3 = bw[3];
            float a[8];
            a[0]=a0.x; a[1]=a0.y; a[2]=a0.z; a[3]=a0.w;
            a[4]=a1.x; a[5]=a1.y; a[6]=a1.z; a[7]=a1.w;
            #pragma unroll
            for (int i = 0; i < 8; i++) {
                u64 aa = pk2(a[i], a[i]);
                acc2[i][0] = fma2(aa, b0, acc2[i][0]);
                acc2[i][1] = fma2(aa, b1, acc2[i][1]);
                acc2[i][2] = fma2(aa, b2, acc2[i][2]);
                acc2[i][3] = fma2(aa, b3, acc2[i][3]);
            }
        }
        __syncthreads();
    }

    #pragma unroll
    for (int i = 0; i < 8; i++) {
        int gr = row0 + tr * 8 + i;
        if (gr < N) {
            float o[8];
            upk2(acc2[i][0], &o[0], &o[1]);
            upk2(acc2[i][1], &o[2], &o[3]);
            upk2(acc2[i][2], &o[4], &o[5]);
            upk2(acc2[i][3], &o[6], &o[7]);
            store_h8(gr, tc, o);
        }
    }
}

// g_hwh = fp16( g_h @ W2 ). Same register-tiled structure, f32x2 FMA.
__global__ void k_gemm2(const float* __restrict__ W, int N) {
    __shared__ __align__(16) float As[16][128];
    __shared__ __align__(16) float Ws[16][64];
    int t  = threadIdx.x;
    int tr = t >> 3;
    int tc = t & 7;
    int row0 = blockIdx.x * 128;

    u64 acc2[8][4];
    #pragma unroll
    for (int i = 0; i < 8; i++)
        #pragma unroll
        for (int j = 0; j < 4; j++) acc2[i][j] = 0ULL;

    for (int kt = 0; kt < HH; kt += 16) {
        {
            int gr = row0 + t;
            float4 v0, v1, v2, v3;
            if (gr < N) {
                const float4* Ar = (const float4*)(g_h + (long)gr * HH + kt);
                v0 = Ar[0]; v1 = Ar[1]; v2 = Ar[2]; v3 = Ar[3];
            } else {
                v0 = make_float4(0.f,0.f,0.f,0.f); v1 = v0; v2 = v0; v3 = v0;
            }
            As[ 0][t] = v0.x; As[ 1][t] = v0.y; As[ 2][t] = v0.z; As[ 3][t] = v0.w;
            As[ 4][t] = v1.x; As[ 5][t] = v1.y; As[ 6][t] = v1.z; As[ 7][t] = v1.w;
            As[ 8][t] = v2.x; As[ 9][t] = v2.y; As[10][t] = v2.z; As[11][t] = v2.w;
            As[12][t] = v3.x; As[13][t] = v3.y; As[14][t] = v3.z; As[15][t] = v3.w;
        }
        {
            const float4* Wg = (const float4*)(W + kt * 64);
            ((float4*)Ws)[t]       = Wg[t];
            ((float4*)Ws)[t + 128] = Wg[t + 128];
        }
        __syncthreads();
        #pragma unroll
        for (int k = 0; k < 16; k++) {
            float4 a0 = *(const float4*)&As[k][tr * 8];
            float4 a1 = *(const float4*)&As[k][tr * 8 + 4];
            const u64* bw = (const u64*)&Ws[k][tc * 8];
            u64 b0 = bw[0], b1 = bw[1], b2 = bw[2], b3 = bw[3];
            float a[8];
            a[0]=a0.x; a[1]=a0.y; a[2]=a0.z; a[3]=a0.w;
            a[4]=a1.x; a[5]=a1.y; a[6]=a1.z; a[7]=a1.w;
            #pragma unroll
            for (int i = 0; i < 8; i++) {
                u64 aa = pk2(a[i], a[i]);
                acc2[i][0] = fma2(aa, b0, acc2[i][0]);
                acc2[i][1] = fma2(aa, b1, acc2[i][1]);
                acc2[i][2] = fma2(aa, b2, acc2[i][2]);
                acc2[i][3] = fma2(aa, b3, acc2[i][3]);
            }
        }
        __syncthreads();
    }

    #pragma unroll
    for (int i = 0; i < 8; i++) {
        int gr = row0 + tr * 8 + i;
        if (gr < N) {
            float o[8];
            upk2(acc2[i][0], &o[0], &o[1]);
            upk2(acc2[i][1], &o[2], &o[3]);
            upk2(acc2[i][2], &o[4], &o[5]);
            upk2(acc2[i][3], &o[6], &o[7]);
            store_h8(gr, tc, o);
        }
    }
}

// ---------------------------------------------------------------------------
// Pull-based aggregation, one WARP per node: each lane owns 2 features
// (4B = half2 per neighbor; 32 lanes cover one 128B row = exactly 1 line per
// gather instruction). Unroll x8 keeps 8 independent gathers in flight.
// POOL=false: g_h[n] = relu(agg + b)   (fp32)
// POOL=true : red_add relu(agg + b) into g_pool[batch[n]].
__device__ __forceinline__ void acc_h2(float2& acc, unsigned u, float c) {
    __half2 h = *(__half2*)&u;
    float2 f = __half22float2(h);
    acc.x = fmaf(f.x, c, acc.x);
    acc.y = fmaf(f.y, c, acc.y);
}

template<bool POOL>
__global__ void k_aggregate(const float* __restrict__ b,
                            const int* __restrict__ batch, int N) {
    int n = blockIdx.x * 8 + (threadIdx.x >> 5);
    int lane = threadIdx.x & 31;        // feature pair [2*lane, 2*lane+1]
    if (n >= N) return;
    const unsigned* hwh = (const unsigned*)g_hwh;   // row = 32 unsigned
    float dn = g_dis[n];
    float dn2 = dn * dn;
    float2 acc = make_float2(0.f, 0.f);
    acc_h2(acc, __ldg(&hwh[n * 32 + lane]), dn2);   // self-loop term

    int s = g_rowstart[n];
    int e = g_rowstart[n + 1];
    int i = s;
    for (; i + 8 <= e; i += 8) {
        int2 a0 = g_adjc[i];
        int2 a1 = g_adjc[i + 1];
        int2 a2 = g_adjc[i + 2];
        int2 a3 = g_adjc[i + 3];
        int2 a4 = g_adjc[i + 4];
        int2 a5 = g_adjc[i + 5];
        int2 a6 = g_adjc[i + 6];
        int2 a7 = g_adjc[i + 7];
        unsigned u0 = __ldg(&hwh[a0.x * 32 + lane]);
        unsigned u1 = __ldg(&hwh[a1.x * 32 + lane]);
        unsigned u2 = __ldg(&hwh[a2.x * 32 + lane]);
        unsigned u3 = __ldg(&hwh[a3.x * 32 + lane]);
        unsigned u4 = __ldg(&hwh[a4.x * 32 + lane]);
        unsigned u5 = __ldg(&hwh[a5.x * 32 + lane]);
        unsigned u6 = __ldg(&hwh[a6.x * 32 + lane]);
        unsigned u7 = __ldg(&hwh[a7.x * 32 + lane]);
        acc_h2(acc, u0, __int_as_float(a0.y));
        acc_h2(acc, u1, __int_as_float(a1.y));
        acc_h2(acc, u2, __int_as_float(a2.y));
        acc_h2(acc, u3, __int_as_float(a3.y));
        acc_h2(acc, u4, __int_as_float(a4.y));
        acc_h2(acc, u5, __int_as_float(a5.y));
        acc_h2(acc, u6, __int_as_float(a6.y));
        acc_h2(acc, u7, __int_as_float(a7.y));
    }
    for (; i < e; i++) {
        int2 a0 = g_adjc[i];
        unsigned u0 = __ldg(&hwh[a0.x * 32 + lane]);
        acc_h2(acc, u0, __int_as_float(a0.y));
    }

    float2 bb = ((const float2*)b)[lane];
    float2 o;
    o.x = fmaxf(acc.x + bb.x, 0.0f);
    o.y = fmaxf(acc.y + bb.y, 0.0f);

    if (POOL) {
        int g = batch[n];
        red_add_v2(&((float2*)g_pool)[g * 32 + lane], o.x, o.y);
        if (lane == 0) atomicAdd(&g_cnt[g], 1.0f);
    } else {
        ((float2*)g_h)[n * 32 + lane] = o;
    }
}

// ---------------------------------------------------------------------------
__global__ void k_head(const float* __restrict__ Wf1,
                       const float* __restrict__ bf1,
                       const float* __restrict__ Wf2,
                       const float* __restrict__ bf2,
                       float* __restrict__ out) {
    __shared__ float W1s[HH * DOUTT];
    __shared__ float b1s[DOUTT];
    __shared__ float W2s[DOUTT * CC];
    __shared__ float b2s[CC];
    for (int i = threadIdx.x; i < HH * DOUTT; i += blockDim.x) W1s[i] = Wf1[i];
    if (threadIdx.x < DOUTT) b1s[threadIdx.x] = bf1[threadIdx.x];
    if (threadIdx.x < DOUTT * CC) W2s[threadIdx.x] = Wf2[threadIdx.x];
    if (threadIdx.x < CC) b2s[threadIdx.x] = bf2[threadIdx.x];
    __syncthreads();
    int g = threadIdx.x;
    if (g >= GG) return;
    float inv = 1.0f / fmaxf(g_cnt[g], 1.0f);
    float m[HH];
    #pragma unroll
    for (int k = 0; k < HH; k++) m[k] = g_pool[g * HH + k] * inv;
    float o0 = b2s[0], o1 = b2s[1];
    #pragma unroll
    for (int j = 0; j < DOUTT; j++) {
        float a = b1s[j];
        #pragma unroll
        for (int k = 0; k < HH; k++) a = fmaf(m[k], W1s[k * DOUTT + j], a);
        a = fmaxf(a, 0.0f);
        o0 = fmaf(a, W2s[j * CC + 0], o0);
        o1 = fmaf(a, W2s[j * CC + 1], o1);
    }
    float mx = fmaxf(o0, o1);
    float l = mx + logf(expf(o0 - mx) + expf(o1 - mx));
    out[g * CC + 0] = o0 - l;
    out[g * CC + 1] = o1 - l;
}

// ---------------------------------------------------------------------------
extern "C" void kernel_launch(void* const* d_in, const int* in_sizes, int n_in,
                              void* d_out, int out_size) {
    const float* x     = (const float*)d_in[0];
    const int*   ei    = (const int*)d_in[1];
    const int*   batch = (const int*)d_in[2];
    int idx = (n_in >= 14 && in_sizes[3] == 1) ? 4 : 3;
    const float* W_in = (const float*)d_in[idx++];
    const float* b_in = (const float*)d_in[idx++];
    const float* W1   = (const float*)d_in[idx++];
    const float* b1   = (const float*)d_in[idx++];
    const float* W2   = (const float*)d_in[idx++];
    const float* b2   = (const float*)d_in[idx++];
    const float* Wf1  = (const float*)d_in[idx++];
    const float* bf1  = (const float*)d_in[idx++];
    const float* Wf2  = (const float*)d_in[idx++];
    const float* bf2  = (const float*)d_in[idx++];

    int N = in_sizes[0] / DIN;
    int E = in_sizes[1] / 2;
    const int* src = ei;
    const int* dst = ei + E;

    // One-time stream/event setup.
    static cudaStream_t sB = nullptr;
    static cudaEvent_t evFork = nullptr, evJoin = nullptr;
    if (sB == nullptr) {
        cudaStreamCreateWithFlags(&sB, cudaStreamNonBlocking);
        cudaEventCreateWithFlags(&evFork, cudaEventDisableTiming);
        cudaEventCreateWithFlags(&evJoin, cudaEventDisableTiming);
    }

    // Fork: CSR build on side stream, GEMM chain on main stream.
    cudaEventRecord(evFork, 0);
    cudaStreamWaitEvent(sB, evFork, 0);

    // --- side stream: CSR build ---
    k_init<<<(NN + 255) / 256, 256, 0, sB>>>();
    k_degree<<<(E + 255) / 256, 256, 0, sB>>>(src, dst, E);
    k_scan<<<1, SCAN_T, 0, sB>>>(N);
    k_fill_adj<<<(E + 255) / 256, 256, 0, sB>>>(src, dst, E);
    cudaEventRecord(evJoin, sB);

    int gblocks = (N + 127) / 128;

    // --- main stream: g_hwh = fp16( relu(x @ W_in + b_in) @ W1 ) ---
    k_gemm_fused<<<gblocks, 128>>>(x, W_in, b_in, W1, N);

    // Join: aggregation needs both CSR and g_hwh.
    cudaStreamWaitEvent(0, evJoin, 0);

    // conv 1 aggregate -> g_h (fp32), one warp per node
    k_aggregate<false><<<(N + 7) / 8, 256>>>(b1, nullptr, N);

    // conv 2
    k_gemm2<<<gblocks, 128>>>(W2, N);
    // conv 2 aggregate fused with mean-pool accumulation
    k_aggregate<true><<<(N + 7) / 8, 256>>>(b2, batch, N);

    // head
    k_head<<<1, 256>>>(Wf1, bf1, Wf2, bf2, (float*)d_out);
}